// round 17
// baseline (speedup 1.0000x reference)
#include <cuda_runtime.h>
#include <cuda_fp16.h>
#include <cstdint>

#define Bn 16
#define Tn 256
#define Cn 6
#define En 512
#define Hn 8
#define HD 64
#define NTOK (Bn*Tn*Cn)      // 24576
#define NHEADS (Bn*Hn*Cn)    // 768

// ---- device-global scratch (no allocations allowed) ----
// g_xr, g_wr: fp16, k-pair-interleaved per 16-half block (pair order {0,4,1,5,2,6,3,7}).
// g_q/g_k/g_v/g_y: fp16, plain layout.
__device__ __half g_q[(size_t)NHEADS * Tn * HD];
__device__ __half g_k[(size_t)NHEADS * Tn * HD];
__device__ __half g_v[(size_t)NHEADS * Tn * HD];
__device__ __half g_y[(size_t)NTOK * En];
__device__ __half g_xr[(size_t)NTOK * En];
__device__ __half g_wr[(size_t)4 * En * En];

// ---------------------------------------------------------------------------
__device__ __forceinline__ uint32_t h2rn(float a, float b) {
    __half2 h = __floats2half2_rn(a, b);
    return *reinterpret_cast<uint32_t*>(&h);
}

__device__ __forceinline__ void cpasync16(void* smem_dst, const void* gsrc) {
    uint32_t s = (uint32_t)__cvta_generic_to_shared(smem_dst);
    asm volatile("cp.async.ca.shared.global [%0], [%1], 16;\n" :: "r"(s), "l"(gsrc));
}

__device__ __forceinline__ void mma_f16(float c[4], const uint32_t a[4], const uint32_t b[2]) {
    asm volatile(
        "mma.sync.aligned.m16n8k16.row.col.f32.f16.f16.f32 "
        "{%0,%1,%2,%3}, {%4,%5,%6,%7}, {%8,%9}, {%0,%1,%2,%3};"
        : "+f"(c[0]), "+f"(c[1]), "+f"(c[2]), "+f"(c[3])
        : "r"(a[0]), "r"(a[1]), "r"(a[2]), "r"(a[3]), "r"(b[0]), "r"(b[1]));
}

// ---------------------------------------------------------------------------
// Prepass: fp32 -> fp16(rn), pair-interleaved per 16-half k-block:
// out half order: k0,k1, k8,k9, k2,k3, k10,k11, k4,k5, k12,k13, k6,k7, k14,k15
// ---------------------------------------------------------------------------
#define NXB (NTOK * En / 16)     // 786432
#define NWB (4 * En * En / 16)   // 65536

__global__ void round_all_kernel(const float* __restrict__ x,
                                 const float* __restrict__ Wq, const float* __restrict__ Wk,
                                 const float* __restrict__ Wv, const float* __restrict__ Wp) {
    int i = blockIdx.x * 256 + threadIdx.x;
    const float* src;
    __half* dst;
    if (i < NXB) {
        src = x + (size_t)i * 16;
        dst = g_xr + (size_t)i * 16;
    } else {
        int j = i - NXB;
        int w = j >> 14;
        int off = j & 16383;
        src = ((w == 0) ? Wq : (w == 1) ? Wk : (w == 2) ? Wv : Wp) + (size_t)off * 16;
        dst = g_wr + (size_t)j * 16;
    }
    float4 v0 = ((const float4*)src)[0];
    float4 v1 = ((const float4*)src)[1];
    float4 v2 = ((const float4*)src)[2];
    float4 v3 = ((const float4*)src)[3];
    uint4 o0, o1;
    o0.x = h2rn(v0.x, v0.y);
    o0.y = h2rn(v2.x, v2.y);
    o0.z = h2rn(v0.z, v0.w);
    o0.w = h2rn(v2.z, v2.w);
    o1.x = h2rn(v1.x, v1.y);
    o1.y = h2rn(v3.x, v3.y);
    o1.z = h2rn(v1.z, v1.w);
    o1.w = h2rn(v3.z, v3.w);
    ((uint4*)dst)[0] = o0;
    ((uint4*)dst)[1] = o1;
}

// ---------------------------------------------------------------------------
// fp16 GEMM cores. CTA tile 128x256, 8 warps (2M x 4N), warp tile 64x64,
// m16n8k16, BK=32 halves, double-buffered cp.async.
//  - interleaved operand: stride 48 halves -> LDS.64 frags (CF verified)
//  - plain operand:       stride 40 halves -> LDS.32 frags (CF verified)
// ---------------------------------------------------------------------------
#define RSI 48
#define RSP 40
#define BKH 32
#define NKI (En / BKH)   // 16

template<int ROWS>
__device__ __forceinline__ void load_tile_h(__half* dst, const __half* gsrc,
                                            int stride, int k0, int tid) {
    #pragma unroll
    for (int it = 0; it < ROWS / 64; it++) {
        int idx = it * 256 + tid;       // ROWS rows x 4 chunks of 8 halves
        int m   = idx >> 2;
        int kc  = idx & 3;
        cpasync16(dst + m * stride + kc * 8, gsrc + (size_t)m * En + k0 + kc * 8);
    }
}

// Both operands interleaved (qkv). Warp tile 64x64: acc[4][8][4].
__device__ __forceinline__ void compute_tile_ii(const __half* As, const __half* Bs,
                                                float acc[4][8][4],
                                                int wm, int wn, int gr, int ctl) {
    #pragma unroll
    for (int ks = 0; ks < 2; ks++) {
        uint32_t a[4][4], b[8][2];
        #pragma unroll
        for (int mi = 0; mi < 4; mi++) {
            const __half* p = As + (wm * 64 + mi * 16 + gr) * RSI + ks * 16 + 4 * ctl;
            uint2 lo = *(const uint2*)p;
            uint2 hi = *(const uint2*)(p + 8 * RSI);
            a[mi][0] = lo.x; a[mi][1] = hi.x; a[mi][2] = lo.y; a[mi][3] = hi.y;
        }
        #pragma unroll
        for (int ni = 0; ni < 8; ni++) {
            const __half* p = Bs + (wn * 64 + ni * 8 + gr) * RSI + ks * 16 + 4 * ctl;
            uint2 bb = *(const uint2*)p;
            b[ni][0] = bb.x; b[ni][1] = bb.y;
        }
        #pragma unroll
        for (int mi = 0; mi < 4; mi++)
            #pragma unroll
            for (int ni = 0; ni < 8; ni++)
                mma_f16(acc[mi][ni], a[mi], b[ni]);
    }
}

// A plain, B interleaved (proj). Warp tile 64x64.
__device__ __forceinline__ void compute_tile_pi(const __half* As, const __half* Bs,
                                                float acc[4][8][4],
                                                int wm, int wn, int gr, int ctl) {
    #pragma unroll
    for (int ks = 0; ks < 2; ks++) {
        uint32_t a[4][4], b[8][2];
        #pragma unroll
        for (int mi = 0; mi < 4; mi++) {
            const __half* p = As + (wm * 64 + mi * 16 + gr) * RSP + ks * 16 + 2 * ctl;
            a[mi][0] = *(const uint32_t*)p;
            a[mi][1] = *(const uint32_t*)(p + 8 * RSP);
            a[mi][2] = *(const uint32_t*)(p + 8);
            a[mi][3] = *(const uint32_t*)(p + 8 * RSP + 8);
        }
        #pragma unroll
        for (int ni = 0; ni < 8; ni++) {
            const __half* p = Bs + (wn * 64 + ni * 8 + gr) * RSI + ks * 16 + 4 * ctl;
            uint2 bb = *(const uint2*)p;
            b[ni][0] = bb.x; b[ni][1] = bb.y;
        }
        #pragma unroll
        for (int mi = 0; mi < 4; mi++)
            #pragma unroll
            for (int ni = 0; ni < 8; ni++)
                mma_f16(acc[mi][ni], a[mi], b[ni]);
    }
}

#define GEMM_MAINLOOP_H(gA, gB, SA, SB, CT, AsP, BsP, RA, RB)                  \
    load_tile_h<RA>(AsP, gA, SA, 0, tid);                                      \
    load_tile_h<RB>(BsP, gB, SB, 0, tid);                                      \
    asm volatile("cp.async.commit_group;\n" ::);                               \
    _Pragma("unroll 1")                                                        \
    for (int kt = 0; kt < NKI; kt++) {                                         \
        if (kt + 1 < NKI) {                                                    \
            load_tile_h<RA>(AsP + ((kt + 1) & 1) * RA * SA, gA, SA, (kt + 1) * BKH, tid); \
            load_tile_h<RB>(BsP + ((kt + 1) & 1) * RB * SB, gB, SB, (kt + 1) * BKH, tid); \
            asm volatile("cp.async.commit_group;\n" ::);                       \
            asm volatile("cp.async.wait_group 1;\n" ::);                       \
        } else {                                                               \
            asm volatile("cp.async.wait_group 0;\n" ::);                       \
        }                                                                      \
        __syncthreads();                                                       \
        CT(AsP + (kt & 1) * RA * SA, BsP + (kt & 1) * RB * SB, acc, wm, wn, gr, ctl); \
        __syncthreads();                                                       \
    }

#define QKV_SMEM  ((2 * 128 * RSI + 2 * 256 * RSI) * 2)   // 73728 B
#define PROJ_SMEM ((2 * 128 * RSP + 2 * 256 * RSI) * 2)   // 69632 B

// ---------------------------------------------------------------------------
// QKV: y = x @ W^T + b -> per-head (b,h,c,t,d) fp16.
// grid = (192, 6): mm = y>>1, f0 = (y&1)*256.  CTA tile 128x256.
// ---------------------------------------------------------------------------
__global__ void __launch_bounds__(256, 1)
qkv_mma(const float* __restrict__ bq, const float* __restrict__ bk,
        const float* __restrict__ bv)
{
    extern __shared__ __half dsm_q[];
    __half* As = dsm_q;                    // [2][128*RSI]
    __half* Bs = dsm_q + 2 * 128 * RSI;    // [2][256*RSI]

    const int tid = threadIdx.x, lane = tid & 31, warp = tid >> 5;
    const int wm = warp & 1, wn = warp >> 1;
    const int gr = lane >> 2, ctl = lane & 3;

    const int m0 = blockIdx.x * 128;
    const int mm = blockIdx.y >> 1;
    const int f0 = (blockIdx.y & 1) * 256;

    const __half* gA = g_xr + (size_t)m0 * En;
    const __half* gB = g_wr + (size_t)mm * En * En + (size_t)f0 * En;
    const float* bias = (mm == 0) ? bq : (mm == 1) ? bk : bv;
    __half* gout = (mm == 0) ? g_q : (mm == 1) ? g_k : g_v;

    float acc[4][8][4];
    #pragma unroll
    for (int i = 0; i < 4; i++)
        #pragma unroll
        for (int j = 0; j < 8; j++)
            #pragma unroll
            for (int l = 0; l < 4; l++) acc[i][j][l] = 0.f;

    GEMM_MAINLOOP_H(gA, gB, RSI, RSI, compute_tile_ii, As, Bs, 128, 256)

    const int fbase = f0 + wn * 64;
    #pragma unroll
    for (int mi = 0; mi < 4; mi++) {
        #pragma unroll
        for (int half = 0; half < 2; half++) {
            int r = m0 + wm * 64 + mi * 16 + gr + half * 8;
            int b = r / (Tn * Cn);
            int rem = r - b * (Tn * Cn);
            int t = rem / Cn;
            int cc = rem - t * Cn;
            #pragma unroll
            for (int ni = 0; ni < 8; ni++) {
                int f = fbase + ni * 8 + 2 * ctl;
                int h = f >> 6, d = f & 63;
                uint32_t o = h2rn(acc[mi][ni][half * 2 + 0] + bias[f],
                                  acc[mi][ni][half * 2 + 1] + bias[f + 1]);
                size_t idx = ((((size_t)b * Hn + h) * Cn + cc) * Tn + t) * HD + d;
                *(uint32_t*)(gout + idx) = o;
            }
        }
    }
}

// ---------------------------------------------------------------------------
// Output projection: out(f32) = g_y(f16 plain) @ Wp(f16 interleaved)^T + bp.
// grid = (192, 2).  CTA tile 128x256.
// ---------------------------------------------------------------------------
__global__ void __launch_bounds__(256, 1)
proj_mma(const float* __restrict__ bp, float* __restrict__ out)
{
    extern __shared__ __half dsm_p[];
    __half* As = dsm_p;                    // [2][128*RSP]
    __half* Bs = dsm_p + 2 * 128 * RSP;    // [2][256*RSI]

    const int tid = threadIdx.x, lane = tid & 31, warp = tid >> 5;
    const int wm = warp & 1, wn = warp >> 1;
    const int gr = lane >> 2, ctl = lane & 3;

    const int m0 = blockIdx.x * 128;
    const int f0 = blockIdx.y * 256;

    const __half* gA = g_y + (size_t)m0 * En;
    const __half* gB = g_wr + (size_t)3 * En * En + (size_t)f0 * En;

    float acc[4][8][4];
    #pragma unroll
    for (int i = 0; i < 4; i++)
        #pragma unroll
        for (int j = 0; j < 8; j++)
            #pragma unroll
            for (int l = 0; l < 4; l++) acc[i][j][l] = 0.f;

    GEMM_MAINLOOP_H(gA, gB, RSP, RSI, compute_tile_pi, As, Bs, 128, 256)

    #pragma unroll
    for (int mi = 0; mi < 4; mi++) {
        #pragma unroll
        for (int half = 0; half < 2; half++) {
            int r = m0 + wm * 64 + mi * 16 + gr + half * 8;
            #pragma unroll
            for (int ni = 0; ni < 8; ni++) {
                int col = f0 + wn * 64 + ni * 8 + 2 * ctl;
                float2 o;
                o.x = acc[mi][ni][half * 2 + 0] + bp[col];
                o.y = acc[mi][ni][half * 2 + 1] + bp[col + 1];
                *(float2*)(out + (size_t)r * En + col) = o;
            }
        }
    }
}

// ---------------------------------------------------------------------------
// fp16 MMA attention (unchanged from round 16 — verified correct).
// ---------------------------------------------------------------------------
#define RSK 72
#define RSV 264
#define ATTN_SMEM ((256 * RSK + 64 * RSV) * 2)   // 70656 B

__global__ void __launch_bounds__(256, 1)
attn_kernel()
{
    extern __shared__ __half smh[];
    __half* Ks = smh;                   // [256][RSK]
    __half* Vs = smh + 256 * RSK;       // [64][RSV]  (transposed: [d][s])

    const int hh = blockIdx.x;
    const int c  = hh % Cn;
    const int bh = hh / Cn;
    const int h  = bh % Hn;
    const int b  = bh / Hn;

    const __half* qp = g_q + (size_t)hh * Tn * HD;
    const __half* kp = g_k + (size_t)hh * Tn * HD;
    const __half* vp = g_v + (size_t)hh * Tn * HD;

    const int tid  = threadIdx.x;
    const int lane = tid & 31, warp = tid >> 5;
    const int gr   = lane >> 2, ctl = lane & 3;
    const int r0   = warp * 32;

    #pragma unroll
    for (int it = 0; it < 8; it++) {
        int idx = it * 256 + tid;
        int row = idx >> 3, kc = idx & 7;
        cpasync16(Ks + row * RSK + kc * 8, kp + row * HD + kc * 8);
    }
    asm volatile("cp.async.commit_group;\n" ::);

    const __half2* vp2 = (const __half2*)vp;
    #pragma unroll 4
    for (int it = 0; it < 32; it++) {
        int idx = it * 256 + tid;
        int dp = idx & 31;
        int s  = idx >> 5;
        __half2 v = vp2[(size_t)s * 32 + dp];
        Vs[(2 * dp) * RSV + s]     = __low2half(v);
        Vs[(2 * dp + 1) * RSV + s] = __high2half(v);
    }

    const uint32_t* qp32 = (const uint32_t*)qp;
    uint32_t aq[2][4][4];
    #pragma unroll
    for (int mi = 0; mi < 2; mi++)
        #pragma unroll
        for (int ks = 0; ks < 4; ks++) {
            int row = r0 + mi * 16 + gr;
            aq[mi][ks][0] = qp32[row * 32 + ks * 8 + ctl];
            aq[mi][ks][1] = qp32[(row + 8) * 32 + ks * 8 + ctl];
            aq[mi][ks][2] = qp32[row * 32 + ks * 8 + ctl + 4];
            aq[mi][ks][3] = qp32[(row + 8) * 32 + ks * 8 + ctl + 4];
        }

    asm volatile("cp.async.wait_group 0;\n" ::);
    __syncthreads();

    float oacc[2][8][4];
    #pragma unroll
    for (int mi = 0; mi < 2; mi++)
        #pragma unroll
        for (int dt = 0; dt < 8; dt++)
            #pragma unroll
            for (int e = 0; e < 4; e++) oacc[mi][dt][e] = 0.f;
    float lsum[2][2] = {{0.f, 0.f}, {0.f, 0.f}};

    const int ntiles = (warp >> 1) + 1;

    #pragma unroll 1
    for (int jt = 0; jt < ntiles; jt++) {
        const int j0 = jt * 64;
        #pragma unroll
        for (int ntp = 0; ntp < 4; ntp++) {
            float s2[2][2][4];
            #pragma unroll
            for (int mi = 0; mi < 2; mi++)
                #pragma unroll
                for (int j = 0; j < 2; j++)
                    #pragma unroll
                    for (int e = 0; e < 4; e++) s2[mi][j][e] = 0.f;

            #pragma unroll
            for (int ks = 0; ks < 4; ks++) {
                uint32_t bk2[2][2];
                #pragma unroll
                for (int j = 0; j < 2; j++) {
                    const uint32_t* kr = (const uint32_t*)
                        (Ks + (j0 + (ntp * 2 + j) * 8 + gr) * RSK + ks * 16);
                    bk2[j][0] = kr[ctl];
                    bk2[j][1] = kr[ctl + 4];
                }
                #pragma unroll
                for (int mi = 0; mi < 2; mi++)
                    #pragma unroll
                    for (int j = 0; j < 2; j++)
                        mma_f16(s2[mi][j], aq[mi][ks], bk2[j]);
            }

            uint32_t ap[2][4];
            #pragma unroll
            for (int mi = 0; mi < 2; mi++) {
                const int row0 = r0 + mi * 16 + gr;
                #pragma unroll
                for (int j = 0; j < 2; j++) {
                    const int col = j0 + (ntp * 2 + j) * 8 + 2 * ctl;
                    float p00 = (col     <= row0)     ? __expf(s2[mi][j][0] * 0.125f) : 0.f;
                    float p01 = (col + 1 <= row0)     ? __expf(s2[mi][j][1] * 0.125f) : 0.f;
                    float p10 = (col     <= row0 + 8) ? __expf(s2[mi][j][2] * 0.125f) : 0.f;
                    float p11 = (col + 1 <= row0 + 8) ? __expf(s2[mi][j][3] * 0.125f) : 0.f;
                    uint32_t hlo = h2rn(p00, p01);
                    uint32_t hhi = h2rn(p10, p11);
                    ap[mi][j * 2 + 0] = hlo;
                    ap[mi][j * 2 + 1] = hhi;
                    float2 flo = __half22float2(*reinterpret_cast<__half2*>(&hlo));
                    float2 fhi = __half22float2(*reinterpret_cast<__half2*>(&hhi));
                    lsum[mi][0] += flo.x + flo.y;
                    lsum[mi][1] += fhi.x + fhi.y;
                }
            }

            #pragma unroll
            for (int dt = 0; dt < 8; dt++) {
                const uint32_t* vr = (const uint32_t*)
                    (Vs + (dt * 8 + gr) * RSV + j0 + ntp * 16);
                uint32_t bv[2];
                bv[0] = vr[ctl];
                bv[1] = vr[ctl + 4];
                #pragma unroll
                for (int mi = 0; mi < 2; mi++)
                    mma_f16(oacc[mi][dt], ap[mi], bv);
            }
        }
    }

    float inv[2][2];
    #pragma unroll
    for (int mi = 0; mi < 2; mi++)
        #pragma unroll
        for (int hf = 0; hf < 2; hf++) {
            float l = lsum[mi][hf];
            l += __shfl_xor_sync(0xffffffff, l, 1);
            l += __shfl_xor_sync(0xffffffff, l, 2);
            inv[mi][hf] = 1.f / l;
        }

    #pragma unroll
    for (int mi = 0; mi < 2; mi++)
        #pragma unroll
        for (int hf = 0; hf < 2; hf++) {
            int trow = r0 + mi * 16 + gr + 8 * hf;
            uint32_t* yp = (uint32_t*)g_y
                + (size_t)(b * Tn + trow) * 1536 + (h * Cn + c) * 32;
            #pragma unroll
            for (int dt = 0; dt < 8; dt++)
                yp[dt * 4 + ctl] = h2rn(oacc[mi][dt][hf * 2 + 0] * inv[mi][hf],
                                        oacc[mi][dt][hf * 2 + 1] * inv[mi][hf]);
        }
}

// ---------------------------------------------------------------------------
extern "C" void kernel_launch(void* const* d_in, const int* in_sizes, int n_in,
                              void* d_out, int out_size)
{
    const float* x  = (const float*)d_in[0];
    const float* Wq = (const float*)d_in[1];
    const float* bq = (const float*)d_in[2];
    const float* Wk = (const float*)d_in[3];
    const float* bk = (const float*)d_in[4];
    const float* Wv = (const float*)d_in[5];
    const float* bv = (const float*)d_in[6];
    const float* Wp = (const float*)d_in[7];
    const float* bp = (const float*)d_in[8];
    float* out = (float*)d_out;

    cudaFuncSetAttribute(qkv_mma,  cudaFuncAttributeMaxDynamicSharedMemorySize, QKV_SMEM);
    cudaFuncSetAttribute(proj_mma, cudaFuncAttributeMaxDynamicSharedMemorySize, PROJ_SMEM);
    cudaFuncSetAttribute(attn_kernel, cudaFuncAttributeMaxDynamicSharedMemorySize, ATTN_SMEM);

    round_all_kernel<<<(NXB + NWB) / 256, 256>>>(x, Wq, Wk, Wv, Wp);
    qkv_mma<<<dim3(NTOK / 128, 6), 256, QKV_SMEM>>>(bq, bk, bv);
    attn_kernel<<<NHEADS, 256, ATTN_SMEM>>>();
    proj_mma<<<dim3(NTOK / 128, 2), 256, PROJ_SMEM>>>(bp, out);
}